// round 2
// baseline (speedup 1.0000x reference)
#include <cuda_runtime.h>

#define NQ      12
#define DIM     4096
#define NLAYERS 2
#define THREADS 256
#define EPT     16          // elements per thread (DIM / THREADS)

// XOR swizzle: conflict-free for both the 16t+j and 256j+t access patterns.
__device__ __forceinline__ int sw(int s) { return s ^ ((s >> 5) & 31); }

__global__ __launch_bounds__(THREADS)
void qc_kernel(const float* __restrict__ x,
               const float* __restrict__ th,
               float* __restrict__ out)
{
    __shared__ float st[DIM];
    __shared__ float csA[3][NQ], snA[3][NQ];   // [0]=encoding, [1]=layer0, [2]=layer1
    __shared__ float red[(THREADS / 32) * NQ];

    const int b    = blockIdx.x;
    const int tid  = threadIdx.x;
    const int lane = tid & 31;

    // ---- angle precompute, spread across 3 warps ----
    if (tid < 96) {
        int w = tid >> 5;
        if (lane < NQ) {
            float ang = (w == 0) ? x[b * NQ + lane] : th[(w - 1) * NQ + lane];
            float s_, c_;
            sincosf(0.5f * ang, &s_, &c_);
            csA[w][lane] = c_;
            snA[w][lane] = s_;
        }
    }
    __syncthreads();

    // ---- angle encoding == product state, built directly in registers (ownership A) ----
    // s = 16*tid + j : j bits = qubits 0-3, tid bits 0-7 = qubits 4-11
    float v[EPT];
    {
        float h = 1.0f;
        #pragma unroll
        for (int i = 0; i < 8; i++)
            h *= ((tid >> i) & 1) ? snA[0][4 + i] : csA[0][4 + i];
        #pragma unroll
        for (int j = 0; j < EPT; j++) {
            float a = h;
            #pragma unroll
            for (int q = 0; q < 4; q++)
                a *= ((j >> q) & 1) ? snA[0][q] : csA[0][q];
            v[j] = a;
        }
    }

    // ---- variational layers ----
    #pragma unroll
    for (int layer = 0; layer < NLAYERS; layer++) {
        const float* C = csA[1 + layer];
        const float* S = snA[1 + layer];

        // qubits 0-3: register butterflies (ownership A, j bit q)
        #pragma unroll
        for (int rb = 0; rb < 4; rb++) {
            const float c = C[rb], s = S[rb];
            #pragma unroll
            for (int m = 0; m < EPT / 2; m++) {
                const int low = (1 << rb) - 1;
                const int j0  = ((m & ~low) << 1) | (m & low);
                const int j1  = j0 | (1 << rb);
                float a0 = v[j0], a1 = v[j1];
                v[j0] = fmaf(c, a0, -s * a1);
                v[j1] = fmaf(s, a0,  c * a1);
            }
        }

        // qubits 4-8: lane-bit butterflies via warp shuffle
        #pragma unroll
        for (int q = 4; q < 9; q++) {
            const float c = C[q], s = S[q];
            const int   bit = (lane >> (q - 4)) & 1;
            #pragma unroll
            for (int j = 0; j < EPT; j++) {
                float o = __shfl_xor_sync(0xFFFFFFFFu, v[j], 1 << (q - 4));
                v[j] = bit ? fmaf(s, o, c * v[j])
                           : fmaf(c, v[j], -s * o);
            }
        }

        // ---- transpose A -> B (conflict-free both ways with swizzle) ----
        __syncthreads();                      // prior st consumers done
        #pragma unroll
        for (int j = 0; j < EPT; j++)
            st[sw(tid * EPT + j)] = v[j];
        __syncthreads();
        #pragma unroll
        for (int j = 0; j < EPT; j++)
            v[j] = st[sw(j * THREADS + tid)];  // ownership B: s = 256j + tid

        // qubits 9-11: register butterflies (ownership B, j bit rb -> qubit 8+rb)
        #pragma unroll
        for (int rb = 1; rb < 4; rb++) {
            const float c = C[8 + rb], s = S[8 + rb];
            #pragma unroll
            for (int m = 0; m < EPT / 2; m++) {
                const int low = (1 << rb) - 1;
                const int j0  = ((m & ~low) << 1) | (m & low);
                const int j1  = j0 | (1 << rb);
                float a0 = v[j0], a1 = v[j1];
                v[j0] = fmaf(c, a0, -s * a1);
                v[j1] = fmaf(s, a0,  c * a1);
            }
        }

        // ---- CNOT ring: fused permutation scatter (2-way bank conflict max) ----
        __syncthreads();                      // transpose reads done before overwrite
        #pragma unroll
        for (int j = 0; j < EPT; j++) {
            int s0 = j * THREADS + tid;
            unsigned p = (unsigned)s0;
            p ^= p << 1; p ^= p << 2; p ^= p << 4; p ^= p << 8;
            p &= 0xFFFu;
            int dst = s0 ^ (int)((p << 1) & 0xFFEu) ^ (int)(p >> 11);
            st[sw(dst)] = v[j];
        }
        __syncthreads();
        // gather back to ownership A (conflict-free)
        #pragma unroll
        for (int j = 0; j < EPT; j++)
            v[j] = st[sw(tid * EPT + j)];
    }

    // ---- Pauli-Z expectations ----
    // qubits 0-3 depend on j (per-element sign); qubits 4-11 depend only on tid.
    float P = 0.0f;
    float a0q = 0.0f, a1q = 0.0f, a2q = 0.0f, a3q = 0.0f;
    #pragma unroll
    for (int j = 0; j < EPT; j++) {
        float pv = v[j] * v[j];
        P += pv;
        a0q += ((j >> 0) & 1) ? -pv : pv;
        a1q += ((j >> 1) & 1) ? -pv : pv;
        a2q += ((j >> 2) & 1) ? -pv : pv;
        a3q += ((j >> 3) & 1) ? -pv : pv;
    }
    float acc[NQ];
    acc[0] = a0q; acc[1] = a1q; acc[2] = a2q; acc[3] = a3q;
    #pragma unroll
    for (int q = 4; q < NQ; q++)
        acc[q] = ((tid >> (q - 4)) & 1) ? -P : P;

    // warp reduce, then cross-warp via smem
    #pragma unroll
    for (int q = 0; q < NQ; q++) {
        #pragma unroll
        for (int off = 16; off; off >>= 1)
            acc[q] += __shfl_down_sync(0xFFFFFFFFu, acc[q], off);
    }
    const int w = tid >> 5;
    if (lane == 0) {
        #pragma unroll
        for (int q = 0; q < NQ; q++) red[w * NQ + q] = acc[q];
    }
    __syncthreads();
    if (tid < NQ) {
        float r = 0.0f;
        #pragma unroll
        for (int w2 = 0; w2 < THREADS / 32; w2++) r += red[w2 * NQ + tid];
        out[b * NQ + tid] = r;
    }
}

extern "C" void kernel_launch(void* const* d_in, const int* in_sizes, int n_in,
                              void* d_out, int out_size)
{
    const float* x  = (const float*)d_in[0];   // (1024, 12) float32
    const float* th = (const float*)d_in[1];   // (2, 12)    float32
    float* o = (float*)d_out;                  // (1024, 12) float32
    (void)in_sizes; (void)n_in; (void)out_size;
    qc_kernel<<<1024, THREADS>>>(x, th, o);
}

// round 3
// speedup vs baseline: 1.1702x; 1.1702x over previous
#include <cuda_runtime.h>

#define NQ      12
#define DIM     4096
#define NLAYERS 2
#define THREADS 256
#define EPT     16          // elements per thread

// XOR swizzle; conflict-free for ownership patterns A, B, C (C via tid4->bit9 mapping)
__device__ __forceinline__ int sw(int s) { return s ^ ((s >> 5) & 31); }

// Ownership address maps (all bijections (tid,j) <-> s)
__device__ __forceinline__ int sA(int tid, int j) { return tid * 16 + j; }            // j = bits 0-3
__device__ __forceinline__ int sB(int tid, int j) { return j * 256 + tid; }           // j = bits 8-11
__device__ __forceinline__ int sC(int tid, int j) {                                    // j = bits 4-7
    return (tid & 15) | (j << 4)
         | (((tid >> 5) & 1) << 8)  | (((tid >> 4) & 1) << 9)
         | (((tid >> 6) & 1) << 10) | (((tid >> 7) & 1) << 11);
}

// RY butterfly over register bit rb (qubit = qbase + rb)
#define REG_BF4(Cq, Sq, QBASE)                                             \
    _Pragma("unroll")                                                      \
    for (int rb = 0; rb < 4; rb++) {                                       \
        const float c = (Cq)[(QBASE) + rb], s = (Sq)[(QBASE) + rb];        \
        _Pragma("unroll")                                                  \
        for (int m = 0; m < 8; m++) {                                      \
            const int low = (1 << rb) - 1;                                 \
            const int j0  = ((m & ~low) << 1) | (m & low);                 \
            const int j1  = j0 | (1 << rb);                                \
            float a0 = v[j0], a1 = v[j1];                                  \
            v[j0] = fmaf(c, a0, -s * a1);                                  \
            v[j1] = fmaf(s, a0,  c * a1);                                  \
        }                                                                  \
    }

__global__ __launch_bounds__(THREADS)
void qc_kernel(const float* __restrict__ x,
               const float* __restrict__ th,
               float* __restrict__ out)
{
    __shared__ float st[DIM];
    __shared__ float csA[3][NQ], snA[3][NQ];   // [0]=encoding, [1]=layer0, [2]=layer1
    __shared__ float red[(THREADS / 32) * NQ];

    const int b    = blockIdx.x;
    const int tid  = threadIdx.x;
    const int lane = tid & 31;

    // ---- angle precompute across 3 warps ----
    if (tid < 96) {
        int w = tid >> 5;
        if (lane < NQ) {
            float ang = (w == 0) ? x[b * NQ + lane] : th[(w - 1) * NQ + lane];
            float s_, c_;
            sincosf(0.5f * ang, &s_, &c_);
            csA[w][lane] = c_;
            snA[w][lane] = s_;
        }
    }
    __syncthreads();

    // ---- product state directly in registers (ownership A) ----
    // s = 16*tid + j : tid bit i -> qubit 4+i, j bit q -> qubit q
    float v[EPT];
    {
        float h = 1.0f;
        #pragma unroll
        for (int i = 0; i < 8; i++)
            h *= ((tid >> i) & 1) ? snA[0][4 + i] : csA[0][4 + i];
        float lo[4], hi[4];
        #pragma unroll
        for (int m = 0; m < 4; m++) {
            lo[m] = ((m & 1) ? snA[0][0] : csA[0][0]) * ((m & 2) ? snA[0][1] : csA[0][1]);
            hi[m] = ((m & 1) ? snA[0][2] : csA[0][2]) * ((m & 2) ? snA[0][3] : csA[0][3]);
        }
        #pragma unroll
        for (int j = 0; j < EPT; j++)
            v[j] = h * lo[j & 3] * hi[j >> 2];
    }

    // ---- variational layers: all-register butterflies + smem transposes ----
    #pragma unroll
    for (int layer = 0; layer < NLAYERS; layer++) {
        const float* C = csA[1 + layer];
        const float* S = snA[1 + layer];

        // qubits 0-3 in ownership A
        REG_BF4(C, S, 0)

        // transpose A -> C  (write A: conflict-free; read C: conflict-free)
        #pragma unroll
        for (int j = 0; j < EPT; j++) st[sw(sA(tid, j))] = v[j];
        __syncthreads();
        #pragma unroll
        for (int j = 0; j < EPT; j++) v[j] = st[sw(sC(tid, j))];

        // qubits 4-7 in ownership C
        REG_BF4(C, S, 4)

        // transpose C -> B  (write C hits own read addresses: no barrier before)
        #pragma unroll
        for (int j = 0; j < EPT; j++) st[sw(sC(tid, j))] = v[j];
        __syncthreads();
        #pragma unroll
        for (int j = 0; j < EPT; j++) v[j] = st[sw(sB(tid, j))];

        // qubits 8-11 in ownership B
        REG_BF4(C, S, 8)

        if (layer == 0) {
            // CNOT ring as fused bit-linear permutation, scatter B -> gather A
            __syncthreads();                  // all B reads done before scatter
            #pragma unroll
            for (int j = 0; j < EPT; j++) {
                int s0 = sB(tid, j);
                unsigned p = (unsigned)s0;
                p ^= p << 1; p ^= p << 2; p ^= p << 4; p ^= p << 8;
                p &= 0xFFFu;
                int dst = s0 ^ (int)((p << 1) & 0xFFEu) ^ (int)(p >> 11);
                st[sw(dst)] = v[j];
            }
            __syncthreads();
            #pragma unroll
            for (int j = 0; j < EPT; j++) v[j] = st[sw(sA(tid, j))];
        }
        // layer 1: skip the permutation — fold it into the expectation signs
    }

    // ---- expectations in ownership B with permuted-sign trick ----
    // bit_q(P(s)): q=1..7 -> parity(tid bits 0..q)  [thread-constant]
    //              q=8..11 -> parity(tid) ^ parity(j & ((1<<(q-7))-1))
    //              q=0    -> parity(tid>>1) ^ parity(j)
    float P = 0.f, g1 = 0.f, g3 = 0.f, g7 = 0.f, gF = 0.f;
    #pragma unroll
    for (int j = 0; j < EPT; j++) {
        float p = v[j] * v[j];
        P  += p;
        g1 += (__popc(j & 1)  & 1) ? -p : p;
        g3 += (__popc(j & 3)  & 1) ? -p : p;
        g7 += (__popc(j & 7)  & 1) ? -p : p;
        gF += (__popc(j & 15) & 1) ? -p : p;
    }
    const int pt  = __popc(tid) & 1;
    const int pt1 = __popc(tid >> 1) & 1;

    float acc[NQ];
    acc[0] = pt1 ? -gF : gF;
    #pragma unroll
    for (int q = 1; q < 8; q++) {
        int sq = __popc(tid & ((1 << (q + 1)) - 1)) & 1;
        acc[q] = sq ? -P : P;
    }
    acc[8]  = pt ? -g1 : g1;
    acc[9]  = pt ? -g3 : g3;
    acc[10] = pt ? -g7 : g7;
    acc[11] = pt ? -gF : gF;

    // warp reduce, then cross-warp via smem
    #pragma unroll
    for (int q = 0; q < NQ; q++) {
        #pragma unroll
        for (int off = 16; off; off >>= 1)
            acc[q] += __shfl_down_sync(0xFFFFFFFFu, acc[q], off);
    }
    const int w = tid >> 5;
    if (lane == 0) {
        #pragma unroll
        for (int q = 0; q < NQ; q++) red[w * NQ + q] = acc[q];
    }
    __syncthreads();
    if (tid < NQ) {
        float r = 0.0f;
        #pragma unroll
        for (int w2 = 0; w2 < THREADS / 32; w2++) r += red[w2 * NQ + tid];
        out[b * NQ + tid] = r;
    }
}

extern "C" void kernel_launch(void* const* d_in, const int* in_sizes, int n_in,
                              void* d_out, int out_size)
{
    const float* x  = (const float*)d_in[0];   // (1024, 12) float32
    const float* th = (const float*)d_in[1];   // (2, 12)    float32
    float* o = (float*)d_out;                  // (1024, 12) float32
    (void)in_sizes; (void)n_in; (void)out_size;
    qc_kernel<<<1024, THREADS>>>(x, th, o);
}

// round 4
// speedup vs baseline: 1.3000x; 1.1109x over previous
#include <cuda_runtime.h>

#define NQ      12
#define DIM     4096
#define NLAYERS 2
#define THREADS 256
#define EPT     16
#define STSZ    4224        // 4096 + padding headroom (max addr 4222)

// RY butterfly over register bit rb (qubit = qbase + rb)
#define REG_BF4(Cq, Sq, QBASE)                                             \
    _Pragma("unroll")                                                      \
    for (int rb = 0; rb < 4; rb++) {                                       \
        const float c = (Cq)[(QBASE) + rb], s = (Sq)[(QBASE) + rb];        \
        _Pragma("unroll")                                                  \
        for (int m = 0; m < 8; m++) {                                      \
            const int low = (1 << rb) - 1;                                 \
            const int j0  = ((m & ~low) << 1) | (m & low);                 \
            const int j1  = j0 | (1 << rb);                                \
            float a0 = v[j0], a1 = v[j1];                                  \
            v[j0] = fmaf(c, a0, -s * a1);                                  \
            v[j1] = fmaf(s, a0,  c * a1);                                  \
        }                                                                  \
    }

__global__ __launch_bounds__(THREADS, 4)
void qc_kernel(const float* __restrict__ x,
               const float* __restrict__ th,
               float* __restrict__ out)
{
    __shared__ float st[STSZ];
    __shared__ float csA[3][NQ], snA[3][NQ];
    __shared__ float red[(THREADS / 32) * NQ];

    const int b    = blockIdx.x;
    const int tid  = threadIdx.x;
    const int lane = tid & 31;

    // padded-layout bases: addr = base + compile-time offset(j)
    const int baseA = tid * 16 + (tid >> 1);                 // + j
    const int baseB = tid + (tid >> 5);                      // + 264*j
    const int tb    = ((tid >> 5) & 1) | (((tid >> 4) & 1) << 1)
                    | (((tid >> 6) & 1) << 2) | (((tid >> 7) & 1) << 3);
    const int baseC = (tid & 15) + 264 * tb;                 // + 16*j + (j>>1)

    // ---- angle precompute across 3 warps ----
    if (tid < 96) {
        int w = tid >> 5;
        if (lane < NQ) {
            float ang = (w == 0) ? x[b * NQ + lane] : th[(w - 1) * NQ + lane];
            float s_, c_;
            sincosf(0.5f * ang, &s_, &c_);
            csA[w][lane] = c_;
            snA[w][lane] = s_;
        }
    }
    __syncthreads();

    // ---- product state in registers (ownership A: s = 16*tid + j) ----
    float v[EPT];
    {
        float h = 1.0f;
        #pragma unroll
        for (int i = 0; i < 8; i++)
            h *= ((tid >> i) & 1) ? snA[0][4 + i] : csA[0][4 + i];
        float lo[4], hi[4];
        #pragma unroll
        for (int m = 0; m < 4; m++) {
            lo[m] = ((m & 1) ? snA[0][0] : csA[0][0]) * ((m & 2) ? snA[0][1] : csA[0][1]);
            hi[m] = ((m & 1) ? snA[0][2] : csA[0][2]) * ((m & 2) ? snA[0][3] : csA[0][3]);
        }
        #pragma unroll
        for (int j = 0; j < EPT; j++)
            v[j] = h * lo[j & 3] * hi[j >> 2];
    }

    // ---- CNOT-ring scatter constants (bit-linear permutation, padded layout) ----
    // dst-addr(t,j) = base_{parity(j)} + 264*(J(j) ^ 15*P_t)
    unsigned px = tid; px ^= px << 1; px ^= px << 2; px ^= px << 4;   // prefix-xor, 8 bits
    const int Pt   = (px >> 7) & 1;
    const int T    = (tid ^ (int)(px << 1)) & 0xFE;
    const int t0p  = (tid & 1) ^ Pt;
    const int sb   = T + (T >> 5);
    const int pb0  = sb + t0p;
    const int pb1  = sb + (t0p ^ 1);
    const int msk  = Pt ? 15 : 0;

    // ---- variational layers ----
    #pragma unroll
    for (int layer = 0; layer < NLAYERS; layer++) {
        const float* C = csA[1 + layer];
        const float* S = snA[1 + layer];

        REG_BF4(C, S, 0)                        // qubits 0-3 (ownership A)

        #pragma unroll
        for (int j = 0; j < EPT; j++) st[baseA + j] = v[j];
        __syncthreads();
        #pragma unroll
        for (int j = 0; j < EPT; j++) v[j] = st[baseC + 16 * j + (j >> 1)];

        REG_BF4(C, S, 4)                        // qubits 4-7 (ownership C)

        #pragma unroll
        for (int j = 0; j < EPT; j++) st[baseC + 16 * j + (j >> 1)] = v[j];
        __syncthreads();
        #pragma unroll
        for (int j = 0; j < EPT; j++) v[j] = st[baseB + 264 * j];

        REG_BF4(C, S, 8)                        // qubits 8-11 (ownership B)

        if (layer == 0) {
            __syncthreads();                    // all B reads done before scatter
            #pragma unroll
            for (int j = 0; j < EPT; j++) {
                const int j0 = j & 1, j1 = (j >> 1) & 1, j2 = (j >> 2) & 1, j3 = (j >> 3) & 1;
                const int Jv = j0 | ((j1 ^ j0) << 1) | ((j2 ^ j1 ^ j0) << 2)
                             | ((j3 ^ j2 ^ j1 ^ j0) << 3);
                const int pj = j0 ^ j1 ^ j2 ^ j3;
                st[(pj ? pb1 : pb0) + 264 * (Jv ^ msk)] = v[j];
            }
            __syncthreads();
            #pragma unroll
            for (int j = 0; j < EPT; j++) v[j] = st[baseA + j];
        }
        // layer 1: permutation folded into expectation signs
    }

    // ---- expectations in ownership B with permuted-sign trick ----
    float P = 0.f, g1 = 0.f, g3 = 0.f, g7 = 0.f, gF = 0.f;
    #pragma unroll
    for (int j = 0; j < EPT; j++) {
        float p = v[j] * v[j];
        P  += p;
        g1 += (__popc(j & 1)  & 1) ? -p : p;
        g3 += (__popc(j & 3)  & 1) ? -p : p;
        g7 += (__popc(j & 7)  & 1) ? -p : p;
        gF += (__popc(j & 15) & 1) ? -p : p;
    }
    const int pt  = __popc(tid) & 1;
    const int pt1 = __popc(tid >> 1) & 1;

    float acc[NQ];
    acc[0] = pt1 ? -gF : gF;
    #pragma unroll
    for (int q = 1; q < 8; q++) {
        int sq = __popc(tid & ((1 << (q + 1)) - 1)) & 1;
        acc[q] = sq ? -P : P;
    }
    acc[8]  = pt ? -g1 : g1;
    acc[9]  = pt ? -g3 : g3;
    acc[10] = pt ? -g7 : g7;
    acc[11] = pt ? -gF : gF;

    #pragma unroll
    for (int q = 0; q < NQ; q++) {
        #pragma unroll
        for (int off = 16; off; off >>= 1)
            acc[q] += __shfl_down_sync(0xFFFFFFFFu, acc[q], off);
    }
    const int w = tid >> 5;
    if (lane == 0) {
        #pragma unroll
        for (int q = 0; q < NQ; q++) red[w * NQ + q] = acc[q];
    }
    __syncthreads();
    if (tid < NQ) {
        float r = 0.0f;
        #pragma unroll
        for (int w2 = 0; w2 < THREADS / 32; w2++) r += red[w2 * NQ + tid];
        out[b * NQ + tid] = r;
    }
}

extern "C" void kernel_launch(void* const* d_in, const int* in_sizes, int n_in,
                              void* d_out, int out_size)
{
    const float* x  = (const float*)d_in[0];   // (1024, 12) float32
    const float* th = (const float*)d_in[1];   // (2, 12)    float32
    float* o = (float*)d_out;                  // (1024, 12) float32
    (void)in_sizes; (void)n_in; (void)out_size;
    qc_kernel<<<1024, THREADS>>>(x, th, o);
}

// round 6
// speedup vs baseline: 1.4345x; 1.1034x over previous
#include <cuda_runtime.h>

#define NQ      12
#define DIM     4096
#define THREADS 256
#define EPT     16
#define STSZ    4352        // max padded addr 4350
typedef unsigned long long ull;

#define SGN2  0x8000000080000000ULL   // packed fp32x2 sign-bit flip
#define NEG1F2 0xBF800000BF800000ULL  // packed (-1.0f, -1.0f)

__device__ __forceinline__ ull pk(float lo, float hi) {
    ull r; asm("mov.b64 %0, {%1, %2};" : "=l"(r) : "f"(lo), "f"(hi)); return r;
}
__device__ __forceinline__ void upk(ull a, float& lo, float& hi) {
    asm("mov.b64 {%0, %1}, %2;" : "=f"(lo), "=f"(hi) : "l"(a));
}
__device__ __forceinline__ ull fma2(ull a, ull b, ull c) {
    ull d; asm("fma.rn.f32x2 %0, %1, %2, %3;" : "=l"(d) : "l"(a), "l"(b), "l"(c)); return d;
}
__device__ __forceinline__ ull mul2(ull a, ull b) {
    ull d; asm("mul.rn.f32x2 %0, %1, %2;" : "=l"(d) : "l"(a), "l"(b)); return d;
}
__device__ __forceinline__ ull add2(ull a, ull b) {
    ull d; asm("add.rn.f32x2 %0, %1, %2;" : "=l"(d) : "l"(a), "l"(b)); return d;
}
__device__ __forceinline__ ull sub2(ull a, ull b) { return fma2(b, NEG1F2, a); }

// packed RY butterfly over register bit rb (qubit = QBASE + rb)
#define REG_BF4P(TC, TS, TNS, QBASE)                                       \
    _Pragma("unroll")                                                      \
    for (int rb = 0; rb < 4; rb++) {                                       \
        const ull c2  = (TC)[(QBASE) + rb];                                \
        const ull s2  = (TS)[(QBASE) + rb];                                \
        const ull ns2 = (TNS)[(QBASE) + rb];                               \
        _Pragma("unroll")                                                  \
        for (int m = 0; m < 8; m++) {                                      \
            const int low = (1 << rb) - 1;                                 \
            const int j0  = ((m & ~low) << 1) | (m & low);                 \
            const int j1  = j0 | (1 << rb);                                \
            ull a0 = v[j0], a1 = v[j1];                                    \
            v[j0] = fma2(c2, a0, mul2(ns2, a1));                           \
            v[j1] = fma2(s2, a0, mul2(c2,  a1));                           \
        }                                                                  \
    }

__global__ __launch_bounds__(THREADS, 3)
void qc_kernel(const float* __restrict__ x,
               const float* __restrict__ th,
               float* __restrict__ out)
{
    __shared__ ull st2[STSZ];
    __shared__ ull enc_c[NQ], enc_s[NQ];
    __shared__ ull th_c[2][NQ], th_s[2][NQ], th_ns[2][NQ];
    __shared__ ull red[(THREADS / 32) * NQ];

    const int b    = blockIdx.x;           // handles batch items 2b, 2b+1
    const int tid  = threadIdx.x;
    const int lane = tid & 31;

    // padded bases (element = float2 = 8B; addr = s + (s>>4), conflict-free A/B/C)
    const int baseA = 17 * tid;                               // + j
    const int baseB = tid + (tid >> 4);                       // + 272*j
    const int tb    = ((tid >> 5) & 1) | (((tid >> 4) & 1) << 1)
                    | (((tid >> 6) & 1) << 2) | (((tid >> 7) & 1) << 3);
    const int baseC = (tid & 15) + 272 * tb;                  // + 17*j

    // ---- angle precompute (packed) ----
    if (tid < NQ) {
        float c0, s0, c1, s1;
        sincosf(0.5f * x[(2 * b) * NQ + tid],     &s0, &c0);
        sincosf(0.5f * x[(2 * b + 1) * NQ + tid], &s1, &c1);
        enc_c[tid] = pk(c0, c1);
        enc_s[tid] = pk(s0, s1);
    } else if (tid >= 32 && tid < 32 + NQ) {
        int q = tid - 32; float s_, c_;
        sincosf(0.5f * th[q], &s_, &c_);
        th_c[0][q] = pk(c_, c_); th_s[0][q] = pk(s_, s_); th_ns[0][q] = pk(-s_, -s_);
    } else if (tid >= 64 && tid < 64 + NQ) {
        int q = tid - 64; float s_, c_;
        sincosf(0.5f * th[NQ + q], &s_, &c_);
        th_c[1][q] = pk(c_, c_); th_s[1][q] = pk(s_, s_); th_ns[1][q] = pk(-s_, -s_);
    }
    __syncthreads();

    // ---- packed product state (ownership A: s = 16*tid + j) ----
    ull v[EPT];
    {
        ull h = ((tid >> 0) & 1) ? enc_s[4] : enc_c[4];
        #pragma unroll
        for (int i = 1; i < 8; i++)
            h = mul2(h, ((tid >> i) & 1) ? enc_s[4 + i] : enc_c[4 + i]);
        ull lo[4], hi[4];
        #pragma unroll
        for (int m = 0; m < 4; m++) {
            lo[m] = mul2((m & 1) ? enc_s[0] : enc_c[0], (m & 2) ? enc_s[1] : enc_c[1]);
            hi[m] = mul2((m & 1) ? enc_s[2] : enc_c[2], (m & 2) ? enc_s[3] : enc_c[3]);
        }
        #pragma unroll
        for (int j = 0; j < EPT; j++)
            v[j] = mul2(mul2(h, lo[j & 3]), hi[j >> 2]);
    }

    // ---- CNOT-ring scatter constants (bit-linear permutation) ----
    unsigned px = tid; px ^= px << 1; px ^= px << 2; px ^= px << 4;
    const int Pt  = (px >> 7) & 1;
    const int T   = (tid ^ (int)(px << 1)) & 0xFE;
    const int t0p = (tid & 1) ^ Pt;
    const int pb0 = T + t0p       + (T >> 4);
    const int pb1 = T + (t0p ^ 1) + (T >> 4);
    const int msk = Pt ? 15 : 0;

    // ---- variational layers ----
    #pragma unroll
    for (int layer = 0; layer < 2; layer++) {
        const ull* C  = th_c[layer];
        const ull* S  = th_s[layer];
        const ull* NS = th_ns[layer];

        REG_BF4P(C, S, NS, 0)                   // qubits 0-3 (A)

        #pragma unroll
        for (int j = 0; j < EPT; j++) st2[baseA + j] = v[j];
        __syncthreads();
        #pragma unroll
        for (int j = 0; j < EPT; j++) v[j] = st2[baseC + 17 * j];

        REG_BF4P(C, S, NS, 4)                   // qubits 4-7 (C)

        #pragma unroll
        for (int j = 0; j < EPT; j++) st2[baseC + 17 * j] = v[j];
        __syncthreads();
        #pragma unroll
        for (int j = 0; j < EPT; j++) v[j] = st2[baseB + 272 * j];

        REG_BF4P(C, S, NS, 8)                   // qubits 8-11 (B)

        if (layer == 0) {
            __syncthreads();                    // all B reads done before scatter
            #pragma unroll
            for (int j = 0; j < EPT; j++) {
                const int j0 = j & 1, j1 = (j >> 1) & 1, j2 = (j >> 2) & 1, j3 = (j >> 3) & 1;
                const int Jv = j0 | ((j1 ^ j0) << 1) | ((j2 ^ j1 ^ j0) << 2)
                             | ((j3 ^ j2 ^ j1 ^ j0) << 3);
                const int pj = j0 ^ j1 ^ j2 ^ j3;
                st2[(pj ? pb1 : pb0) + 272 * (Jv ^ msk)] = v[j];
            }
            __syncthreads();
            #pragma unroll
            for (int j = 0; j < EPT; j++) v[j] = st2[baseA + j];
        }
        // layer 1: ring permutation folded into expectation signs
    }

    // ---- expectations (ownership B) via packed Walsh combine over j ----
    ull a[8], d[8];
    #pragma unroll
    for (int k = 0; k < 8; k++) {
        ull pe = mul2(v[2 * k],     v[2 * k]);
        ull po = mul2(v[2 * k + 1], v[2 * k + 1]);
        a[k] = add2(pe, po);
        d[k] = sub2(pe, po);
    }
    ull P  = add2(add2(add2(a[0], a[1]), add2(a[2], a[3])),
                  add2(add2(a[4], a[5]), add2(a[6], a[7])));
    ull e0 = add2(d[0], d[1]), e1 = add2(d[2], d[3]);
    ull e2 = add2(d[4], d[5]), e3 = add2(d[6], d[7]);
    ull f0 = sub2(d[0], d[1]), f1 = sub2(d[2], d[3]);
    ull f2 = sub2(d[4], d[5]), f3 = sub2(d[6], d[7]);
    ull g1 = add2(add2(e0, e1), add2(e2, e3));
    ull g3 = add2(add2(f0, f1), add2(f2, f3));
    ull g7 = add2(sub2(f0, f1), sub2(f2, f3));
    ull gF = sub2(add2(f0, f3), add2(f1, f2));

    const int pt  = __popc(tid) & 1;
    const int pt1 = __popc(tid >> 1) & 1;

    ull acc[NQ];
    acc[0] = pt1 ? (gF ^ SGN2) : gF;
    #pragma unroll
    for (int q = 1; q < 8; q++) {
        int sq = __popc(tid & ((1 << (q + 1)) - 1)) & 1;
        acc[q] = sq ? (P ^ SGN2) : P;
    }
    acc[8]  = pt ? (g1 ^ SGN2) : g1;
    acc[9]  = pt ? (g3 ^ SGN2) : g3;
    acc[10] = pt ? (g7 ^ SGN2) : g7;
    acc[11] = pt ? (gF ^ SGN2) : gF;

    // packed warp reduce, then cross-warp via smem
    #pragma unroll
    for (int q = 0; q < NQ; q++) {
        #pragma unroll
        for (int off = 16; off; off >>= 1)
            acc[q] = add2(acc[q], __shfl_down_sync(0xFFFFFFFFu, acc[q], off));
    }
    const int w = tid >> 5;
    if (lane == 0) {
        #pragma unroll
        for (int q = 0; q < NQ; q++) red[w * NQ + q] = acc[q];
    }
    __syncthreads();
    if (tid < NQ) {
        ull r = red[tid];
        #pragma unroll
        for (int w2 = 1; w2 < THREADS / 32; w2++) r = add2(r, red[w2 * NQ + tid]);
        float r0, r1; upk(r, r0, r1);
        out[(2 * b) * NQ + tid]     = r0;
        out[(2 * b + 1) * NQ + tid] = r1;
    }
}

extern "C" void kernel_launch(void* const* d_in, const int* in_sizes, int n_in,
                              void* d_out, int out_size)
{
    const float* x  = (const float*)d_in[0];   // (1024, 12) float32
    const float* th = (const float*)d_in[1];   // (2, 12)    float32
    float* o = (float*)d_out;                  // (1024, 12) float32
    (void)in_sizes; (void)n_in; (void)out_size;
    qc_kernel<<<512, THREADS>>>(x, th, o);
}

// round 8
// speedup vs baseline: 1.6124x; 1.1240x over previous
#include <cuda_runtime.h>

#define NQ      12
#define DIM     4096
#define THREADS 256
#define EPT     16
#define STSZ    4352        // max padded addr 4350
typedef unsigned long long ull;

#define SGN2  0x8000000080000000ULL   // packed fp32x2 sign-bit flip

__device__ __forceinline__ ull pk(float lo, float hi) {
    ull r; asm("mov.b64 %0, {%1, %2};" : "=l"(r) : "f"(lo), "f"(hi)); return r;
}
__device__ __forceinline__ void upk(ull a, float& lo, float& hi) {
    asm("mov.b64 {%0, %1}, %2;" : "=f"(lo), "=f"(hi) : "l"(a));
}
__device__ __forceinline__ ull fma2(ull a, ull b, ull c) {
    ull d; asm("fma.rn.f32x2 %0, %1, %2, %3;" : "=l"(d) : "l"(a), "l"(b), "l"(c)); return d;
}
__device__ __forceinline__ ull mul2(ull a, ull b) {
    ull d; asm("mul.rn.f32x2 %0, %1, %2;" : "=l"(d) : "l"(a), "l"(b)); return d;
}
__device__ __forceinline__ ull add2(ull a, ull b) {
    ull d; asm("add.rn.f32x2 %0, %1, %2;" : "=l"(d) : "l"(a), "l"(b)); return d;
}
__device__ __forceinline__ ull sub2(ull a, ull b) { return fma2(b, 0xBF800000BF800000ULL, a); }

// tan-form RY butterfly (deferred cosine): a0' = a0 - t*a1 ; a1' = a1 + t*a0
// exact gate = cos * (a0', a1'); cosines folded into final output scale.
#define REG_BF4T(TT, TNT, QBASE)                                           \
    _Pragma("unroll")                                                      \
    for (int rb = 0; rb < 4; rb++) {                                       \
        const ull t2  = (TT)[(QBASE) + rb];                                \
        const ull nt2 = (TNT)[(QBASE) + rb];                               \
        _Pragma("unroll")                                                  \
        for (int m = 0; m < 8; m++) {                                      \
            const int low = (1 << rb) - 1;                                 \
            const int j0  = ((m & ~low) << 1) | (m & low);                 \
            const int j1  = j0 | (1 << rb);                                \
            ull a0 = v[j0];                                                \
            v[j0] = fma2(nt2, v[j1], a0);                                  \
            v[j1] = fma2(t2,  a0,   v[j1]);                                \
        }                                                                  \
    }

__global__ __launch_bounds__(THREADS, 4)
void qc_kernel(const float* __restrict__ x,
               const float* __restrict__ th,
               float* __restrict__ out)
{
    __shared__ ull st2[STSZ];
    __shared__ ull enc_c[NQ], enc_s[NQ];
    __shared__ ull th_t[2][NQ], th_nt[2][NQ];
    __shared__ float cosv[2 * NQ];
    __shared__ ull red[(THREADS / 32) * NQ];

    const int b    = blockIdx.x;           // batch items 2b, 2b+1
    const int tid  = threadIdx.x;
    const int lane = tid & 31;

    // padded bases (8B elements; addr = s + (s>>4); conflict-free A/B/C)
    const int baseA = 17 * tid;                               // + j
    const int baseB = tid + (tid >> 4);                       // + 272*j
    const int tb    = ((tid >> 5) & 1) | (((tid >> 4) & 1) << 1)
                    | (((tid >> 6) & 1) << 2) | (((tid >> 7) & 1) << 3);
    const int baseC = (tid & 15) + 272 * tb;                  // + 17*j

    // ---- angle precompute ----
    if (tid < NQ) {
        float c0, s0, c1, s1;
        sincosf(0.5f * x[(2 * b) * NQ + tid],     &s0, &c0);
        sincosf(0.5f * x[(2 * b + 1) * NQ + tid], &s1, &c1);
        enc_c[tid] = pk(c0, c1);
        enc_s[tid] = pk(s0, s1);
    } else if (tid >= 32 && tid < 32 + 2 * NQ) {
        int k = tid - 32;                 // k = layer*12 + q
        int layer = k / NQ, q = k % NQ;
        float s_, c_;
        sincosf(0.5f * th[k], &s_, &c_);
        float t_ = s_ / c_;
        th_t[layer][q]  = pk(t_, t_);
        th_nt[layer][q] = pk(-t_, -t_);
        cosv[k] = c_;
    }
    __syncthreads();

    // ---- packed product state (ownership A: s = 16*tid + j) ----
    ull v[EPT];
    {
        ull h = (tid & 1) ? enc_s[4] : enc_c[4];
        #pragma unroll
        for (int i = 1; i < 8; i++)
            h = mul2(h, ((tid >> i) & 1) ? enc_s[4 + i] : enc_c[4 + i]);
        ull lo[4], hi[4];
        #pragma unroll
        for (int m = 0; m < 4; m++) {
            lo[m] = mul2((m & 1) ? enc_s[0] : enc_c[0], (m & 2) ? enc_s[1] : enc_c[1]);
            hi[m] = mul2((m & 1) ? enc_s[2] : enc_c[2], (m & 2) ? enc_s[3] : enc_c[3]);
        }
        #pragma unroll
        for (int j = 0; j < EPT; j++)
            v[j] = mul2(mul2(h, lo[j & 3]), hi[j >> 2]);
    }

    // ---- variational layers (tan-form gates, cosines deferred) ----
    #pragma unroll
    for (int layer = 0; layer < 2; layer++) {
        const ull* T  = th_t[layer];
        const ull* NT = th_nt[layer];

        REG_BF4T(T, NT, 0)                      // qubits 0-3 (A)

        #pragma unroll
        for (int j = 0; j < EPT; j++) st2[baseA + j] = v[j];
        __syncthreads();
        #pragma unroll
        for (int j = 0; j < EPT; j++) v[j] = st2[baseC + 17 * j];

        REG_BF4T(T, NT, 4)                      // qubits 4-7 (C)

        #pragma unroll
        for (int j = 0; j < EPT; j++) st2[baseC + 17 * j] = v[j];
        __syncthreads();
        #pragma unroll
        for (int j = 0; j < EPT; j++) v[j] = st2[baseB + 272 * j];

        REG_BF4T(T, NT, 8)                      // qubits 8-11 (B)

        if (layer == 0) {
            // CNOT ring = bit-linear permutation; scatter B -> gather A
            unsigned px = tid; px ^= px << 1; px ^= px << 2; px ^= px << 4;
            const int Pt  = (px >> 7) & 1;
            const int Tt  = (tid ^ (int)(px << 1)) & 0xFE;
            const int t0p = (tid & 1) ^ Pt;
            const int pb0 = Tt + t0p       + (Tt >> 4);
            const int pb1 = Tt + (t0p ^ 1) + (Tt >> 4);
            const int msk = Pt ? 15 : 0;

            __syncthreads();                    // all B reads done before scatter
            #pragma unroll
            for (int j = 0; j < EPT; j++) {
                const int j0 = j & 1, j1 = (j >> 1) & 1, j2 = (j >> 2) & 1, j3 = (j >> 3) & 1;
                const int Jv = j0 | ((j1 ^ j0) << 1) | ((j2 ^ j1 ^ j0) << 2)
                             | ((j3 ^ j2 ^ j1 ^ j0) << 3);
                const int pj = j0 ^ j1 ^ j2 ^ j3;
                st2[(pj ? pb1 : pb0) + 272 * (Jv ^ msk)] = v[j];
            }
            __syncthreads();
            #pragma unroll
            for (int j = 0; j < EPT; j++) v[j] = st2[baseA + j];
        }
        // layer 1: ring permutation folded into expectation signs
    }

    // ---- expectations (ownership B) via packed Walsh combine ----
    ull a[8], d[8];
    #pragma unroll
    for (int k = 0; k < 8; k++) {
        ull pe = mul2(v[2 * k],     v[2 * k]);
        ull po = mul2(v[2 * k + 1], v[2 * k + 1]);
        a[k] = add2(pe, po);
        d[k] = sub2(pe, po);
    }
    ull P  = add2(add2(add2(a[0], a[1]), add2(a[2], a[3])),
                  add2(add2(a[4], a[5]), add2(a[6], a[7])));
    ull e0 = add2(d[0], d[1]), e1 = add2(d[2], d[3]);
    ull e2 = add2(d[4], d[5]), e3 = add2(d[6], d[7]);
    ull f0 = sub2(d[0], d[1]), f1 = sub2(d[2], d[3]);
    ull f2 = sub2(d[4], d[5]), f3 = sub2(d[6], d[7]);
    ull g1 = add2(add2(e0, e1), add2(e2, e3));
    ull g3 = add2(add2(f0, f1), add2(f2, f3));
    ull g7 = add2(sub2(f0, f1), sub2(f2, f3));
    ull gF = sub2(add2(f0, f3), add2(f1, f2));

    const int pt  = __popc(tid) & 1;
    const int pt1 = __popc(tid >> 1) & 1;

    ull acc[NQ];
    acc[0] = pt1 ? (gF ^ SGN2) : gF;
    #pragma unroll
    for (int q = 1; q < 8; q++) {
        int sq = __popc(tid & ((1 << (q + 1)) - 1)) & 1;
        acc[q] = sq ? (P ^ SGN2) : P;
    }
    acc[8]  = pt ? (g1 ^ SGN2) : g1;
    acc[9]  = pt ? (g3 ^ SGN2) : g3;
    acc[10] = pt ? (g7 ^ SGN2) : g7;
    acc[11] = pt ? (gF ^ SGN2) : gF;

    #pragma unroll
    for (int q = 0; q < NQ; q++) {
        #pragma unroll
        for (int off = 16; off; off >>= 1)
            acc[q] = add2(acc[q], __shfl_down_sync(0xFFFFFFFFu, acc[q], off));
    }
    const int w = tid >> 5;
    if (lane == 0) {
        #pragma unroll
        for (int q = 0; q < NQ; q++) red[w * NQ + q] = acc[q];
    }
    __syncthreads();
    if (tid < NQ) {
        ull r = red[tid];
        #pragma unroll
        for (int w2 = 1; w2 < THREADS / 32; w2++) r = add2(r, red[w2 * NQ + tid]);
        // deferred cosine scale: out *= (prod_{24 gates} cos)^2
        float cs = cosv[0];
        #pragma unroll
        for (int k = 1; k < 2 * NQ; k++) cs *= cosv[k];
        const float sc2 = cs * cs;
        float r0, r1; upk(r, r0, r1);
        out[(2 * b) * NQ + tid]     = r0 * sc2;
        out[(2 * b + 1) * NQ + tid] = r1 * sc2;
    }
}

extern "C" void kernel_launch(void* const* d_in, const int* in_sizes, int n_in,
                              void* d_out, int out_size)
{
    const float* x  = (const float*)d_in[0];   // (1024, 12) float32
    const float* th = (const float*)d_in[1];   // (2, 12)    float32
    float* o = (float*)d_out;                  // (1024, 12) float32
    (void)in_sizes; (void)n_in; (void)out_size;
    qc_kernel<<<512, THREADS>>>(x, th, o);
}